// round 4
// baseline (speedup 1.0000x reference)
#include <cuda_runtime.h>
#include <cuda_bf16.h>
#include <cstdint>

// Problem shape (fixed by the dataset): predict (8,19,512,1024) f32, target (8,512,1024)
#define HW_BITS 19
#define HW (1 << HW_BITS)          // 512*1024 = 524288
#define NCLS 19
#define NIMG 8
#define TOTAL_PX (NIMG * HW)       // 4194304
#define PX_PER_THREAD 4
#define NTHR 256
#define NBLK (TOTAL_PX / (PX_PER_THREAD * NTHR))  // 4096

#define TH1 0.8f
#define TH2 0.5f

// Per-block partials, transposed for coalesced finalize loads:
// g_part[block] = {w_easy, wn_easy, w_mid, wn_mid, w_hard, wn_hard, pad, pad}
__device__ float g_part[NBLK][8];

// Process one buffered group of channels: accumulate exp-sums and select the
// true-class logit. (Macro so everything stays fully unrolled in registers.)
#define PROCESS_GROUP(buf, cbase, cnt)                                   \
    _Pragma("unroll")                                                    \
    for (int j = 0; j < (cnt); j++) {                                    \
        const int c = (cbase) + j;                                       \
        s.x += __expf(buf[j].x); if (t[0] == c) xt[0] = buf[j].x;        \
        s.y += __expf(buf[j].y); if (t[1] == c) xt[1] = buf[j].y;        \
        s.z += __expf(buf[j].z); if (t[2] == c) xt[2] = buf[j].z;        \
        s.w += __expf(buf[j].w); if (t[3] == c) xt[3] = buf[j].w;        \
    }

// ---------------------------------------------------------------------------
// Main streaming kernel: inline dtype detection, double-buffered channel
// groups for high MLP, in-register compare-select for the true-class logit.
// ---------------------------------------------------------------------------
__global__ __launch_bounds__(NTHR) void ohem_main(
    const float* __restrict__ predict,
    const void*  __restrict__ target,
    const float* __restrict__ cw)
{
    const int lane = threadIdx.x & 31;

    // int64-vs-int32 detection: view target as int32; little-endian int64
    // labels in [0,19) have all odd slots zero. P(false pos) = (1/19)^64 ~ 0.
    const int* t32head = (const int*)target;
    int probe = __ldg(t32head + 2 * lane + 1) | __ldg(t32head + 128 + 2 * lane + 1);
    const bool is_i64 = (__ballot_sync(0xffffffffu, probe != 0) == 0u);

    const int tid = blockIdx.x * NTHR + threadIdx.x;
    const long g = (long)tid * PX_PER_THREAD;       // global pixel index

    const int n = (int)(g >> HW_BITS);
    const int p = (int)(g & (HW - 1));

    // --- labels ---
    int t[4];
    if (is_i64) {
        const longlong2* tp = reinterpret_cast<const longlong2*>(
            (const char*)target + (size_t)g * 8);
        longlong2 a = __ldg(tp);
        longlong2 b = __ldg(tp + 1);
        t[0] = (int)a.x; t[1] = (int)a.y; t[2] = (int)b.x; t[3] = (int)b.y;
    } else {
        int4 a = __ldg(reinterpret_cast<const int4*>((const char*)target + (size_t)g * 4));
        t[0] = a.x; t[1] = a.y; t[2] = a.z; t[3] = a.w;
    }

    // --- streaming softmax denominator, double-buffered groups {5,5,5,4} ---
    const float4* base =
        reinterpret_cast<const float4*>(predict) + (((long)n * NCLS) << (HW_BITS - 2)) + (p >> 2);
    const long cs = (long)1 << (HW_BITS - 2);       // channel stride in float4

    float4 s = make_float4(0.f, 0.f, 0.f, 0.f);
    float  xt[4] = {0.f, 0.f, 0.f, 0.f};

    float4 xa[5], xb[5];

    #pragma unroll
    for (int i = 0; i < 5; i++) xa[i] = __ldg(base + (0 + i) * cs);   // c 0..4
    #pragma unroll
    for (int i = 0; i < 5; i++) xb[i] = __ldg(base + (5 + i) * cs);   // c 5..9

    PROCESS_GROUP(xa, 0, 5)
    #pragma unroll
    for (int i = 0; i < 5; i++) xa[i] = __ldg(base + (10 + i) * cs);  // c 10..14

    PROCESS_GROUP(xb, 5, 5)
    #pragma unroll
    for (int i = 0; i < 4; i++) xb[i] = __ldg(base + (15 + i) * cs);  // c 15..18

    PROCESS_GROUP(xa, 10, 5)
    PROCESS_GROUP(xb, 15, 4)

    // --- per-pixel bucket accumulation ---
    float ss[4] = {s.x, s.y, s.z, s.w};
    float acc[6] = {0.f, 0.f, 0.f, 0.f, 0.f, 0.f};

    #pragma unroll
    for (int k = 0; k < PX_PER_THREAD; k++) {
        int tk = t[k];
        if (tk >= 0 && tk < NCLS) {            // excludes IGNORE=255 and garbage
            float nll   = __logf(ss[k]) - xt[k];
            float ptrue = __expf(-nll);        // softmax prob of the true class
            float w     = __ldg(cw + tk);
            int b = (ptrue >= TH1) ? 0 : ((ptrue >= TH2) ? 1 : 2);
            acc[2 * b]     += w;
            acc[2 * b + 1] += w * nll;
        }
    }

    // --- block reduction: warp shuffle, then cross-warp via shared ---
    #pragma unroll
    for (int i = 0; i < 6; i++) {
        #pragma unroll
        for (int off = 16; off > 0; off >>= 1)
            acc[i] += __shfl_down_sync(0xffffffffu, acc[i], off);
    }

    __shared__ float sm[NTHR / 32][6];
    const int wid = threadIdx.x >> 5;
    if (lane == 0) {
        #pragma unroll
        for (int i = 0; i < 6; i++) sm[wid][i] = acc[i];
    }
    __syncthreads();
    if (threadIdx.x < 6) {
        float v = 0.f;
        #pragma unroll
        for (int wi = 0; wi < NTHR / 32; wi++) v += sm[wi][threadIdx.x];
        g_part[blockIdx.x][threadIdx.x] = v;
    }
}

// ---------------------------------------------------------------------------
// Finalize: single pass over [block][8] partials (coalesced float4 pairs),
// per-component double reduction, emit scalar loss.
// ---------------------------------------------------------------------------
__global__ __launch_bounds__(NTHR) void finalize_kernel(float* __restrict__ out) {
    double acc[6] = {0, 0, 0, 0, 0, 0};

    for (int b = threadIdx.x; b < NBLK; b += NTHR) {
        const float4* p = reinterpret_cast<const float4*>(g_part[b]);
        float4 f0 = p[0];
        float4 f1 = p[1];
        acc[0] += (double)f0.x; acc[1] += (double)f0.y;
        acc[2] += (double)f0.z; acc[3] += (double)f0.w;
        acc[4] += (double)f1.x; acc[5] += (double)f1.y;
    }

    __shared__ double smem[NTHR];
    double comp[6];
    for (int i = 0; i < 6; i++) {
        smem[threadIdx.x] = acc[i];
        __syncthreads();
        for (int off = NTHR / 2; off > 0; off >>= 1) {
            if (threadIdx.x < off) smem[threadIdx.x] += smem[threadIdx.x + off];
            __syncthreads();
        }
        comp[i] = smem[0];
        __syncthreads();
    }

    if (threadIdx.x == 0) {
        double loss = 0.0;
        #pragma unroll
        for (int b = 0; b < 3; b++) {
            double den = comp[2 * b];
            if (den < 1e-12) den = 1e-12;
            loss += comp[2 * b + 1] / den;
        }
        out[0] = (float)loss;
    }
}

// ---------------------------------------------------------------------------
extern "C" void kernel_launch(void* const* d_in, const int* in_sizes, int n_in,
                              void* d_out, int out_size) {
    const float* predict = (const float*)d_in[0];
    const void*  target  = d_in[1];
    const float* cw      = (const float*)d_in[2];

    ohem_main<<<NBLK, NTHR>>>(predict, target, cw);
    finalize_kernel<<<1, NTHR>>>((float*)d_out);
}

// round 5
// speedup vs baseline: 1.1824x; 1.1824x over previous
#include <cuda_runtime.h>
#include <cuda_bf16.h>
#include <cstdint>

// Problem shape (fixed by the dataset): predict (8,19,512,1024) f32, target (8,512,1024)
#define HW_BITS 19
#define HW (1 << HW_BITS)          // 512*1024 = 524288
#define NCLS 19
#define NIMG 8
#define TOTAL_PX (NIMG * HW)       // 4194304
#define PX_PER_THREAD 8
#define NTHR 256
#define NBLK (TOTAL_PX / (PX_PER_THREAD * NTHR))  // 2048

#define TH1 0.8f
#define TH2 0.5f

// Per-block partials, transposed for coalesced finalize loads:
// g_part[block] = {w_easy, wn_easy, w_mid, wn_mid, w_hard, wn_hard, pad, pad}
__device__ float g_part[NBLK][8];

// ---------------------------------------------------------------------------
// Main streaming kernel. R1's compiler-friendly loop shape, widened to 8
// pixels/thread via two ADJACENT float4 loads per channel (consumed
// immediately -> low live-range, no spills). Inline dtype detection.
// ---------------------------------------------------------------------------
__global__ __launch_bounds__(NTHR) void ohem_main(
    const float* __restrict__ predict,
    const void*  __restrict__ target,
    const float* __restrict__ cw)
{
    const int lane = threadIdx.x & 31;

    // int64-vs-int32 detection: view target as int32; little-endian int64
    // labels in [0,19) have all odd slots zero. P(false pos) = (1/19)^64 ~ 0.
    const int* t32head = (const int*)target;
    int probe = __ldg(t32head + 2 * lane + 1) | __ldg(t32head + 128 + 2 * lane + 1);
    const bool is_i64 = (__ballot_sync(0xffffffffu, probe != 0) == 0u);

    const int tid = blockIdx.x * NTHR + threadIdx.x;
    const long g = (long)tid * PX_PER_THREAD;       // global pixel index

    const int n = (int)(g >> HW_BITS);
    const int p = (int)(g & (HW - 1));

    // --- labels (8 consecutive pixels, never crossing an image boundary) ---
    int t[8];
    if (is_i64) {
        const longlong2* tp = reinterpret_cast<const longlong2*>(
            (const char*)target + (size_t)g * 8);
        #pragma unroll
        for (int i = 0; i < 4; i++) {
            longlong2 a = __ldg(tp + i);
            t[2 * i]     = (int)a.x;
            t[2 * i + 1] = (int)a.y;
        }
    } else {
        const int4* tp = reinterpret_cast<const int4*>((const char*)target + (size_t)g * 4);
        int4 a = __ldg(tp);
        int4 b = __ldg(tp + 1);
        t[0] = a.x; t[1] = a.y; t[2] = a.z; t[3] = a.w;
        t[4] = b.x; t[5] = b.y; t[6] = b.z; t[7] = b.w;
    }

    // --- streaming softmax denominator (no max subtraction: |logit| <~ 25) ---
    const float4* base =
        reinterpret_cast<const float4*>(predict) + (((long)n * NCLS) << (HW_BITS - 2)) + (p >> 2);
    const long cs = (long)1 << (HW_BITS - 2);       // channel stride in float4

    float s[8]  = {0.f, 0.f, 0.f, 0.f, 0.f, 0.f, 0.f, 0.f};
    float xt[8] = {0.f, 0.f, 0.f, 0.f, 0.f, 0.f, 0.f, 0.f};

    #pragma unroll
    for (int c = 0; c < NCLS; c++) {
        float4 x0 = __ldg(base + c * cs);
        float4 x1 = __ldg(base + c * cs + 1);
        float xv[8] = {x0.x, x0.y, x0.z, x0.w, x1.x, x1.y, x1.z, x1.w};
        #pragma unroll
        for (int k = 0; k < 8; k++) {
            s[k] += __expf(xv[k]);
            if (t[k] == c) xt[k] = xv[k];
        }
    }

    // --- per-pixel bucket accumulation ---
    float acc[6] = {0.f, 0.f, 0.f, 0.f, 0.f, 0.f};

    #pragma unroll
    for (int k = 0; k < PX_PER_THREAD; k++) {
        int tk = t[k];
        if (tk >= 0 && tk < NCLS) {            // excludes IGNORE=255 and garbage
            float nll   = __logf(s[k]) - xt[k];
            float ptrue = __expf(-nll);        // softmax prob of the true class
            float w     = __ldg(cw + tk);
            int b = (ptrue >= TH1) ? 0 : ((ptrue >= TH2) ? 1 : 2);
            acc[2 * b]     += w;
            acc[2 * b + 1] += w * nll;
        }
    }

    // --- block reduction: warp shuffle, then cross-warp via shared ---
    #pragma unroll
    for (int i = 0; i < 6; i++) {
        #pragma unroll
        for (int off = 16; off > 0; off >>= 1)
            acc[i] += __shfl_down_sync(0xffffffffu, acc[i], off);
    }

    __shared__ float sm[NTHR / 32][6];
    const int wid = threadIdx.x >> 5;
    if (lane == 0) {
        #pragma unroll
        for (int i = 0; i < 6; i++) sm[wid][i] = acc[i];
    }
    __syncthreads();
    if (threadIdx.x < 6) {
        float v = 0.f;
        #pragma unroll
        for (int wi = 0; wi < NTHR / 32; wi++) v += sm[wi][threadIdx.x];
        g_part[blockIdx.x][threadIdx.x] = v;
    }
}

// ---------------------------------------------------------------------------
// Finalize: single pass over [block][8] partials (coalesced float4 pairs),
// per-component double reduction, emit scalar loss.
// ---------------------------------------------------------------------------
__global__ __launch_bounds__(NTHR) void finalize_kernel(float* __restrict__ out) {
    double acc[6] = {0, 0, 0, 0, 0, 0};

    for (int b = threadIdx.x; b < NBLK; b += NTHR) {
        const float4* p = reinterpret_cast<const float4*>(g_part[b]);
        float4 f0 = p[0];
        float4 f1 = p[1];
        acc[0] += (double)f0.x; acc[1] += (double)f0.y;
        acc[2] += (double)f0.z; acc[3] += (double)f0.w;
        acc[4] += (double)f1.x; acc[5] += (double)f1.y;
    }

    __shared__ double smem[NTHR];
    double comp[6];
    for (int i = 0; i < 6; i++) {
        smem[threadIdx.x] = acc[i];
        __syncthreads();
        for (int off = NTHR / 2; off > 0; off >>= 1) {
            if (threadIdx.x < off) smem[threadIdx.x] += smem[threadIdx.x + off];
            __syncthreads();
        }
        comp[i] = smem[0];
        __syncthreads();
    }

    if (threadIdx.x == 0) {
        double loss = 0.0;
        #pragma unroll
        for (int b = 0; b < 3; b++) {
            double den = comp[2 * b];
            if (den < 1e-12) den = 1e-12;
            loss += comp[2 * b + 1] / den;
        }
        out[0] = (float)loss;
    }
}

// ---------------------------------------------------------------------------
extern "C" void kernel_launch(void* const* d_in, const int* in_sizes, int n_in,
                              void* d_out, int out_size) {
    const float* predict = (const float*)d_in[0];
    const void*  target  = d_in[1];
    const float* cw      = (const float*)d_in[2];

    ohem_main<<<NBLK, NTHR>>>(predict, target, cw);
    finalize_kernel<<<1, NTHR>>>((float*)d_out);
}